// round 9
// baseline (speedup 1.0000x reference)
#include <cuda_runtime.h>
#include <math.h>

#define T_MAX   10000
#define BATCH   4096
#define CHUNK   32
#define NCHUNKS ((T_MAX + CHUNK - 1) / CHUNK)   // 313
#define PNT     1024
#define PNP     10                               // 1024*10 >= 10000
#define SNT     256                              // scan block threads
#define SGX     (BATCH / (SNT * 4))              // 4

// fp32-cast constants, matching reference's float(np.log(...))
#define LOG_GAMMA_F  0.019802627296179713f    // log(1.02)
#define ALPHA_F     (-1.005033585350145e-05f) // log(0.99)/1000
#define INIT_LOGW_F (-1.3943265327958258f)    // log(0.248)
#define INIT_LOGP_F (-6.907755278982137f)     // log(0.001)
#define EPS_F        1e-12f
#define L1MIN_MAG    27.632f                  // |log(1e-12)| + margin (conservative)

// ---------------- device globals (scratch) -----------------------------------
__device__ float g_m[T_MAX];          // threshold m_t = p/(1-p) - eps
__device__ float g_c[T_MAX];          // u2 filter threshold (2.0 = never triggers)
__device__ float g_prefW[T_MAX + 1];  // exclusive prefix of w_t
__device__ int   g_TcutM1;            // last t with m>0
__device__ int   g_td[BATCH];         // first trigger time per batch elem
__device__ unsigned g_done;           // scan-block completion counter

// ---------------- compensated fp32 (hi,lo) arithmetic -------------------------
struct DS { float hi, lo; };

__device__ __forceinline__ DS ds_make(float h) { DS r; r.hi = h; r.lo = 0.f; return r; }
__device__ __forceinline__ DS ds_of(float2 v)  { DS r; r.hi = v.x; r.lo = v.y; return r; }
__device__ __forceinline__ float2 ds_pack(DS a){ return make_float2(a.hi, a.lo); }

__device__ __forceinline__ DS ds_add(DS a, float b) {
    float s  = a.hi + b;
    float bb = s - a.hi;
    float err = (a.hi - (s - bb)) + (b - bb);
    err += a.lo;
    DS r; r.hi = s + err; r.lo = err - (r.hi - s);
    return r;
}

__device__ __forceinline__ DS ds_add2(DS a, DS b) {
    float s  = a.hi + b.hi;
    float bb = s - a.hi;
    float err = (a.hi - (s - bb)) + (b.hi - bb);
    err += a.lo + b.lo;
    DS r; r.hi = s + err; r.lo = err - (r.hi - s);
    return r;
}

// Warp-inclusive DS scan via shuffles.
__device__ __forceinline__ DS warp_scan_incl(DS v, int lane) {
    #pragma unroll
    for (int ofs = 1; ofs < 32; ofs <<= 1) {
        float h = __shfl_up_sync(0xFFFFFFFFu, v.hi, ofs);
        float l = __shfl_up_sync(0xFFFFFFFFu, v.lo, ofs);
        if (lane >= ofs) { DS t; t.hi = h; t.lo = l; v = ds_add2(v, t); }
    }
    return v;
}

// Block-exclusive DS scan over one value per thread (PNT=1024 = 32 warps).
__device__ __forceinline__ DS block_excl(DS v, float2* swarp, int lane, int wid) {
    DS inc = warp_scan_incl(v, lane);
    if (lane == 31) swarp[wid] = ds_pack(inc);
    __syncthreads();
    if (wid == 0) {
        DS t = ds_of(swarp[lane]);
        t = warp_scan_incl(t, lane);
        swarp[lane] = ds_pack(t);
    }
    __syncthreads();
    DS warpOff = (wid > 0) ? ds_of(swarp[wid - 1]) : ds_make(0.f);
    float hh = __shfl_up_sync(0xFFFFFFFFu, inc.hi, 1);
    float ll = __shfl_up_sync(0xFFFFFFFFu, inc.lo, 1);
    DS exw;
    if (lane > 0) { exw.hi = hh; exw.lo = ll; } else exw = ds_make(0.f);
    DS r = ds_add2(warpOff, exw);
    __syncthreads();   // safe smem reuse by next call
    return r;
}

// ---------------- fused precompute (one block) --------------------------------
__global__ __launch_bounds__(PNT)
void precompute_kernel(const float* __restrict__ acts) {
    __shared__ float2 swarp[32];
    __shared__ int shMax;
    const int tid  = threadIdx.x;
    const int lane = tid & 31;
    const int wid  = tid >> 5;
    const int base = tid * PNP;

    #pragma unroll
    for (int k = 0; k < BATCH / PNT; k++) g_td[tid + k * PNT] = T_MAX;
    if (tid == 0) { shMax = -1; g_done = 0u; }

    // ---- load + per-element f,d ; thread-local DS sum of d ----
    float f[PNP], d[PNP];
    DS locD = ds_make(0.f);
    #pragma unroll
    for (int k = 0; k < PNP; k++) {
        int t = base + k;
        if (t < T_MAX) {
            f[k] = expf(acts[t]);
            d[k] = LOG_GAMMA_F + log1pf(-f[k]);
            locD = ds_add(locD, d[k]);
        } else { f[k] = 0.f; d[k] = 0.f; }
    }
    __syncthreads();
    DS exD = block_excl(locD, swarp, lane, wid);

    // ---- serial pass: local sums of e and w ----
    DS run = ds_add2(ds_make(INIT_LOGW_F), exD);
    DS locE = ds_make(0.f), locW = ds_make(0.f);
    #pragma unroll
    for (int k = 0; k < PNP; k++) {
        int t = base + k;
        if (t < T_MAX) {
            float e = ALPHA_F * f[k] * expf(run.hi);   // uses logw BEFORE update
            locE = ds_add(locE, e);
            run = ds_add(run, d[k]);
            float w = expf(run.hi * 1.0e-3f);          // uses logw AFTER update
            locW = ds_add(locW, w);
        }
    }
    DS exE = block_excl(locE, swarp, lane, wid);
    DS exW = block_excl(locW, swarp, lane, wid);

    // ---- apply pass: m, c, prefW ----
    DS runP = ds_add2(ds_make(INIT_LOGP_F), exE);
    DS runW = exW;
    run = ds_add2(ds_make(INIT_LOGW_F), exD);
    int locMax = -1;
    #pragma unroll
    for (int k = 0; k < PNP; k++) {
        int t = base + k;
        if (t < T_MAX) {
            float p = expf(runP.hi);
            float m = p / (1.0f - p) - EPS_F;
            g_m[t] = m;
            g_c[t] = (m > 0.f) ? expf(-L1MIN_MAG * m) : 2.0f;
            if (m > 0.f) locMax = t;

            float e = ALPHA_F * f[k] * expf(run.hi);
            run = ds_add(run, d[k]);
            float w = expf(run.hi * 1.0e-3f);

            g_prefW[t] = runW.hi;
            runP = ds_add(runP, e);
            runW = ds_add(runW, w);
            if (t == T_MAX - 1) g_prefW[T_MAX] = runW.hi;
        }
    }
    atomicMax(&shMax, locMax);
    __syncthreads();
    if (tid == 0) g_TcutM1 = shMax;
}

// ---------------- scan + fused finalize ---------------------------------------
__global__ __launch_bounds__(SNT)
void scan_kernel(const float* __restrict__ u1, const float* __restrict__ u2,
                 float* __restrict__ out) {
    __shared__ float sm[CHUNK];
    __shared__ float sc[CHUNK];
    __shared__ bool sLast;

    const int tid = threadIdx.x;
    const int t0  = blockIdx.y * CHUNK;
    const int Tc  = g_TcutM1 + 1;

    if (t0 < Tc) {
        if (tid < CHUNK) {
            int tt = t0 + tid;
            sm[tid] = (tt < T_MAX) ? g_m[tt] : -1.0f;
            sc[tid] = (tt < T_MAX) ? g_c[tt] : 2.0f;
        }
        __syncthreads();

        const int b = (blockIdx.x * SNT + tid) * 4;   // 4 consecutive batch elems
        const int n = min(CHUNK, Tc - t0);

        const float* p2 = u2 + (size_t)t0 * BATCH + b;
        const float* p1 = u1 + (size_t)t0 * BATCH + b;

        unsigned done = 0;
        int ht0 = 0, ht1 = 0, ht2 = 0, ht3 = 0;

        for (int i = 0; i < n; ++i) {
            float4 v2 = *(const float4*)p2;
            float ci = sc[i];
            bool q0 = !(done & 1u) && (v2.x + EPS_F) > ci;
            bool q1 = !(done & 2u) && (v2.y + EPS_F) > ci;
            bool q2 = !(done & 4u) && (v2.z + EPS_F) > ci;
            bool q3 = !(done & 8u) && (v2.w + EPS_F) > ci;
            if (q0 | q1 | q2 | q3) {
                float4 v1 = *(const float4*)p1;
                float mi = sm[i];
                int t = t0 + i;
                if (q0 && __logf(v2.x + EPS_F) > mi * __logf(v1.x + EPS_F)) { done |= 1u; ht0 = t; }
                if (q1 && __logf(v2.y + EPS_F) > mi * __logf(v1.y + EPS_F)) { done |= 2u; ht1 = t; }
                if (q2 && __logf(v2.z + EPS_F) > mi * __logf(v1.z + EPS_F)) { done |= 4u; ht2 = t; }
                if (q3 && __logf(v2.w + EPS_F) > mi * __logf(v1.w + EPS_F)) { done |= 8u; ht3 = t; }
                if (done == 0xFu) break;
            }
            p2 += BATCH; p1 += BATCH;
        }
        if (done & 1u) atomicMin(&g_td[b + 0], ht0);
        if (done & 2u) atomicMin(&g_td[b + 1], ht1);
        if (done & 4u) atomicMin(&g_td[b + 2], ht2);
        if (done & 8u) atomicMin(&g_td[b + 3], ht3);
    }

    // ---- completion protocol: last block performs the reduction ----
    __syncthreads();
    if (tid == 0) {
        __threadfence();
        unsigned prev = atomicAdd(&g_done, 1u);
        sLast = (prev == (unsigned)(SGX * NCHUNKS) - 1u);
    }
    __syncthreads();
    if (!sLast) return;
    __threadfence();

    __shared__ double sh[SNT];
    double s = 0.0;
    #pragma unroll
    for (int k = 0; k < BATCH / SNT; k++) {
        int b = tid + k * SNT;
        s += (double)g_prefW[g_td[b]];
    }
    sh[tid] = s;
    __syncthreads();
    #pragma unroll
    for (int ofs = SNT / 2; ofs > 0; ofs >>= 1) {
        if (tid < ofs) sh[tid] += sh[tid + ofs];
        __syncthreads();
    }
    if (tid == 0) out[0] = (float)(sh[0] * (1.0 / (double)BATCH));
}

// ---------------- launch -----------------------------------------------------
extern "C" void kernel_launch(void* const* d_in, const int* in_sizes, int n_in,
                              void* d_out, int out_size) {
    const float* acts = (const float*)d_in[0];
    const float* u1   = (const float*)d_in[1];
    const float* u2   = (const float*)d_in[2];
    float* out = (float*)d_out;

    precompute_kernel<<<1, PNT>>>(acts);
    dim3 grid(SGX, NCHUNKS);
    scan_kernel<<<grid, SNT>>>(u1, u2, out);
}

// round 10
// speedup vs baseline: 1.2096x; 1.2096x over previous
#include <cuda_runtime.h>
#include <math.h>

#define T_MAX   10000
#define BATCH   4096
#define CHUNK   16
#define NCHUNKS ((T_MAX + CHUNK - 1) / CHUNK)   // 625
#define PNT     1024
#define PNP     10                               // 1024*10 >= 10000
#define SNT     256                              // scan block threads
#define SGX     (BATCH / (SNT * 4))              // 4
#define TOTAL_BLOCKS (SGX * NCHUNKS)

// fp32-cast constants, matching reference's float(np.log(...))
#define LOG_GAMMA_F  0.019802627296179713f    // log(1.02)
#define ALPHA_F     (-1.005033585350145e-05f) // log(0.99)/1000
#define INIT_LOGW_F (-1.3943265327958258f)    // log(0.248)
#define INIT_LOGP_F (-6.907755278982137f)     // log(0.001)
#define EPS_F        1e-12f
#define L1MIN_MAG    27.632f                  // |log(1e-12)| + margin (conservative)

// ---------------- device globals (scratch) -----------------------------------
__device__ float g_m[T_MAX];          // threshold m_t = p/(1-p) - eps
__device__ float g_c[T_MAX];          // u2 filter threshold minus slack (2.0 = never)
__device__ float g_prefW[T_MAX + 1];  // exclusive prefix of w_t
__device__ int   g_TcutM1;            // last t with m>0
__device__ int   g_td[BATCH];         // first trigger time per batch elem
__device__ unsigned g_done;           // scan-block completion counter

// ---------------- compensated fp32 (hi,lo) arithmetic -------------------------
struct DS { float hi, lo; };

__device__ __forceinline__ DS ds_make(float h) { DS r; r.hi = h; r.lo = 0.f; return r; }
__device__ __forceinline__ DS ds_of(float2 v)  { DS r; r.hi = v.x; r.lo = v.y; return r; }
__device__ __forceinline__ float2 ds_pack(DS a){ return make_float2(a.hi, a.lo); }

__device__ __forceinline__ DS ds_add(DS a, float b) {
    float s  = a.hi + b;
    float bb = s - a.hi;
    float err = (a.hi - (s - bb)) + (b - bb);
    err += a.lo;
    DS r; r.hi = s + err; r.lo = err - (r.hi - s);
    return r;
}

__device__ __forceinline__ DS ds_add2(DS a, DS b) {
    float s  = a.hi + b.hi;
    float bb = s - a.hi;
    float err = (a.hi - (s - bb)) + (b.hi - bb);
    err += a.lo + b.lo;
    DS r; r.hi = s + err; r.lo = err - (r.hi - s);
    return r;
}

// Warp-inclusive DS scan via shuffles.
__device__ __forceinline__ DS warp_scan_incl(DS v, int lane) {
    #pragma unroll
    for (int ofs = 1; ofs < 32; ofs <<= 1) {
        float h = __shfl_up_sync(0xFFFFFFFFu, v.hi, ofs);
        float l = __shfl_up_sync(0xFFFFFFFFu, v.lo, ofs);
        if (lane >= ofs) { DS t; t.hi = h; t.lo = l; v = ds_add2(v, t); }
    }
    return v;
}

// Block-exclusive DS scan over one value per thread (PNT=1024 = 32 warps).
__device__ __forceinline__ DS block_excl(DS v, float2* swarp, int lane, int wid) {
    DS inc = warp_scan_incl(v, lane);
    if (lane == 31) swarp[wid] = ds_pack(inc);
    __syncthreads();
    if (wid == 0) {
        DS t = ds_of(swarp[lane]);
        t = warp_scan_incl(t, lane);
        swarp[lane] = ds_pack(t);
    }
    __syncthreads();
    DS warpOff = (wid > 0) ? ds_of(swarp[wid - 1]) : ds_make(0.f);
    float hh = __shfl_up_sync(0xFFFFFFFFu, inc.hi, 1);
    float ll = __shfl_up_sync(0xFFFFFFFFu, inc.lo, 1);
    DS exw;
    if (lane > 0) { exw.hi = hh; exw.lo = ll; } else exw = ds_make(0.f);
    DS r = ds_add2(warpOff, exw);
    __syncthreads();   // safe smem reuse by next call
    return r;
}

// ---------------- fused precompute (one block) --------------------------------
__global__ __launch_bounds__(PNT)
void precompute_kernel(const float* __restrict__ acts) {
    __shared__ float2 swarp[32];
    __shared__ int shMax;
    const int tid  = threadIdx.x;
    const int lane = tid & 31;
    const int wid  = tid >> 5;
    const int base = tid * PNP;

    #pragma unroll
    for (int k = 0; k < BATCH / PNT; k++) g_td[tid + k * PNT] = T_MAX;
    if (tid == 0) { shMax = -1; g_done = 0u; }

    // ---- load + per-element f,d ; thread-local DS sum of d ----
    float f[PNP], d[PNP];
    DS locD = ds_make(0.f);
    #pragma unroll
    for (int k = 0; k < PNP; k++) {
        int t = base + k;
        if (t < T_MAX) {
            f[k] = expf(acts[t]);
            d[k] = LOG_GAMMA_F + log1pf(-f[k]);
            locD = ds_add(locD, d[k]);
        } else { f[k] = 0.f; d[k] = 0.f; }
    }
    __syncthreads();
    DS exD = block_excl(locD, swarp, lane, wid);

    // ---- serial pass: local sums of e and w ----
    DS run = ds_add2(ds_make(INIT_LOGW_F), exD);
    DS locE = ds_make(0.f), locW = ds_make(0.f);
    #pragma unroll
    for (int k = 0; k < PNP; k++) {
        int t = base + k;
        if (t < T_MAX) {
            float e = ALPHA_F * f[k] * expf(run.hi);   // uses logw BEFORE update
            locE = ds_add(locE, e);
            run = ds_add(run, d[k]);
            float w = expf(run.hi * 1.0e-3f);          // uses logw AFTER update
            locW = ds_add(locW, w);
        }
    }
    DS exE = block_excl(locE, swarp, lane, wid);
    DS exW = block_excl(locW, swarp, lane, wid);

    // ---- apply pass: m, c, prefW ----
    DS runP = ds_add2(ds_make(INIT_LOGP_F), exE);
    DS runW = exW;
    run = ds_add2(ds_make(INIT_LOGW_F), exD);
    int locMax = -1;
    #pragma unroll
    for (int k = 0; k < PNP; k++) {
        int t = base + k;
        if (t < T_MAX) {
            float p = expf(runP.hi);
            float m = p / (1.0f - p) - EPS_F;
            g_m[t] = m;
            // conservative filter threshold with absolute slack (superset of triggers)
            g_c[t] = (m > 0.f) ? (expf(-L1MIN_MAG * m) - 1.0e-6f) : 2.0f;
            if (m > 0.f) locMax = t;

            float e = ALPHA_F * f[k] * expf(run.hi);
            run = ds_add(run, d[k]);
            float w = expf(run.hi * 1.0e-3f);

            g_prefW[t] = runW.hi;
            runP = ds_add(runP, e);
            runW = ds_add(runW, w);
            if (t == T_MAX - 1) g_prefW[T_MAX] = runW.hi;
        }
    }
    atomicMax(&shMax, locMax);
    __syncthreads();
    if (tid == 0) g_TcutM1 = shMax;
}

// rare-path per-row handler (checks full trigger condition per element)
__device__ __forceinline__ void row_check(float4 v2, const float* p1row,
                                          float mi, float ci, int t,
                                          unsigned& done, int* ht) {
    float4 v1 = *(const float4*)p1row;
    if (!(done & 1u) && v2.x > ci &&
        __logf(v2.x + EPS_F) > mi * __logf(v1.x + EPS_F)) { done |= 1u; ht[0] = t; }
    if (!(done & 2u) && v2.y > ci &&
        __logf(v2.y + EPS_F) > mi * __logf(v1.y + EPS_F)) { done |= 2u; ht[1] = t; }
    if (!(done & 4u) && v2.z > ci &&
        __logf(v2.z + EPS_F) > mi * __logf(v1.z + EPS_F)) { done |= 4u; ht[2] = t; }
    if (!(done & 8u) && v2.w > ci &&
        __logf(v2.w + EPS_F) > mi * __logf(v1.w + EPS_F)) { done |= 8u; ht[3] = t; }
}

// ---------------- scan + fused finalize ---------------------------------------
__global__ __launch_bounds__(SNT)
void scan_kernel(const float* __restrict__ u1, const float* __restrict__ u2,
                 float* __restrict__ out) {
    __shared__ float sm[CHUNK];
    __shared__ float sc[CHUNK];
    __shared__ bool sLast;

    const int tid = threadIdx.x;
    const int t0  = blockIdx.y * CHUNK;
    const int Tc  = g_TcutM1 + 1;

    if (t0 < Tc) {
        if (tid < CHUNK) {
            int tt = t0 + tid;
            bool live = tt < Tc;                // Tc <= T_MAX so reads stay in-bounds
            sm[tid] = live ? g_m[tt] : 0.f;
            sc[tid] = live ? g_c[tt] : 2.0f;    // 2.0 => filter never passes
        }
        __syncthreads();

        const int b = (blockIdx.x * SNT + tid) * 4;   // 4 consecutive batch elems
        const float* p2 = u2 + (size_t)t0 * BATCH + b;
        const float* p1 = u1 + (size_t)t0 * BATCH + b;

        unsigned done = 0;
        int ht[4] = {0, 0, 0, 0};

        #pragma unroll
        for (int g = 0; g < CHUNK / 4; ++g) {
            const int i = g * 4;
            // batch 4 independent 128-bit loads (MLP=4)
            float4 r0 = *(const float4*)(p2 + (size_t)(i + 0) * BATCH);
            float4 r1 = *(const float4*)(p2 + (size_t)(i + 1) * BATCH);
            float4 r2 = *(const float4*)(p2 + (size_t)(i + 2) * BATCH);
            float4 r3 = *(const float4*)(p2 + (size_t)(i + 3) * BATCH);

            float x0 = fmaxf(fmaxf(r0.x, r0.y), fmaxf(r0.z, r0.w));
            float x1 = fmaxf(fmaxf(r1.x, r1.y), fmaxf(r1.z, r1.w));
            float x2 = fmaxf(fmaxf(r2.x, r2.y), fmaxf(r2.z, r2.w));
            float x3 = fmaxf(fmaxf(r3.x, r3.y), fmaxf(r3.z, r3.w));

            bool a0 = x0 > sc[i + 0];
            bool a1 = x1 > sc[i + 1];
            bool a2 = x2 > sc[i + 2];
            bool a3 = x3 > sc[i + 3];

            if (a0 | a1 | a2 | a3) {            // rare path (~10% of groups)
                if (a0) row_check(r0, p1 + (size_t)(i + 0) * BATCH, sm[i + 0], sc[i + 0], t0 + i + 0, done, ht);
                if (a1) row_check(r1, p1 + (size_t)(i + 1) * BATCH, sm[i + 1], sc[i + 1], t0 + i + 1, done, ht);
                if (a2) row_check(r2, p1 + (size_t)(i + 2) * BATCH, sm[i + 2], sc[i + 2], t0 + i + 2, done, ht);
                if (a3) row_check(r3, p1 + (size_t)(i + 3) * BATCH, sm[i + 3], sc[i + 3], t0 + i + 3, done, ht);
                if (done == 0xFu) break;
            }
        }
        if (done & 1u) atomicMin(&g_td[b + 0], ht[0]);
        if (done & 2u) atomicMin(&g_td[b + 1], ht[1]);
        if (done & 4u) atomicMin(&g_td[b + 2], ht[2]);
        if (done & 8u) atomicMin(&g_td[b + 3], ht[3]);
    }

    // ---- completion protocol: last block performs the reduction ----
    __syncthreads();
    if (tid == 0) {
        __threadfence();
        unsigned prev = atomicAdd(&g_done, 1u);
        sLast = (prev == (unsigned)TOTAL_BLOCKS - 1u);
    }
    __syncthreads();
    if (!sLast) return;
    __threadfence();

    __shared__ double sh[SNT];
    double s = 0.0;
    #pragma unroll
    for (int k = 0; k < BATCH / SNT; k++) {
        int b = tid + k * SNT;
        s += (double)g_prefW[g_td[b]];
    }
    sh[tid] = s;
    __syncthreads();
    #pragma unroll
    for (int ofs = SNT / 2; ofs > 0; ofs >>= 1) {
        if (tid < ofs) sh[tid] += sh[tid + ofs];
        __syncthreads();
    }
    if (tid == 0) out[0] = (float)(sh[0] * (1.0 / (double)BATCH));
}

// ---------------- launch -----------------------------------------------------
extern "C" void kernel_launch(void* const* d_in, const int* in_sizes, int n_in,
                              void* d_out, int out_size) {
    const float* acts = (const float*)d_in[0];
    const float* u1   = (const float*)d_in[1];
    const float* u2   = (const float*)d_in[2];
    float* out = (float*)d_out;

    precompute_kernel<<<1, PNT>>>(acts);
    dim3 grid(SGX, NCHUNKS);
    scan_kernel<<<grid, SNT>>>(u1, u2, out);
}

// round 12
// speedup vs baseline: 1.3043x; 1.0783x over previous
#include <cuda_runtime.h>
#include <math.h>

#define T_MAX   10000
#define BATCH   4096
#define CHUNK   8
#define NCHUNKS ((T_MAX + CHUNK - 1) / CHUNK)   // 1250
#define PNT     1024
#define PNP     10                               // 1024*10 >= 10000
#define SNT     256                              // scan block threads
#define SGX     (BATCH / (SNT * 4))              // 4

// fp32-cast constants, matching reference's float(np.log(...))
#define LOG_GAMMA_F  0.019802627296179713f    // log(1.02)
#define ALPHA_F     (-1.005033585350145e-05f) // log(0.99)/1000
#define INIT_LOGW_F (-1.3943265327958258f)    // log(0.248)
#define INIT_LOGP_F (-6.907755278982137f)     // log(0.001)
#define EPS_F        1e-12f
#define L1MIN_MAG    27.632f                  // |log(1e-12)| + margin (conservative)

// ---------------- device globals (scratch) -----------------------------------
__device__ float g_m[T_MAX];          // threshold m_t = p/(1-p) - eps
__device__ float g_c[T_MAX];          // u2 filter threshold minus slack (2.0 = never)
__device__ float g_prefW[T_MAX + 1];  // exclusive prefix of w_t
__device__ int   g_TcutM1;            // last t with m>0
__device__ int   g_td[BATCH];         // first trigger time per batch elem
__device__ unsigned g_done;           // live scan-block completion counter

// ---------------- compensated fp32 (hi,lo) arithmetic -------------------------
struct DS { float hi, lo; };

__device__ __forceinline__ DS ds_make(float h) { DS r; r.hi = h; r.lo = 0.f; return r; }
__device__ __forceinline__ DS ds_of(float2 v)  { DS r; r.hi = v.x; r.lo = v.y; return r; }
__device__ __forceinline__ float2 ds_pack(DS a){ return make_float2(a.hi, a.lo); }

__device__ __forceinline__ DS ds_add(DS a, float b) {
    float s  = a.hi + b;
    float bb = s - a.hi;
    float err = (a.hi - (s - bb)) + (b - bb);
    err += a.lo;
    DS r; r.hi = s + err; r.lo = err - (r.hi - s);
    return r;
}

__device__ __forceinline__ DS ds_add2(DS a, DS b) {
    float s  = a.hi + b.hi;
    float bb = s - a.hi;
    float err = (a.hi - (s - bb)) + (b.hi - bb);
    err += a.lo + b.lo;
    DS r; r.hi = s + err; r.lo = err - (r.hi - s);
    return r;
}

// Warp-inclusive DS scan via shuffles.
__device__ __forceinline__ DS warp_scan_incl(DS v, int lane) {
    #pragma unroll
    for (int ofs = 1; ofs < 32; ofs <<= 1) {
        float h = __shfl_up_sync(0xFFFFFFFFu, v.hi, ofs);
        float l = __shfl_up_sync(0xFFFFFFFFu, v.lo, ofs);
        if (lane >= ofs) { DS t; t.hi = h; t.lo = l; v = ds_add2(v, t); }
    }
    return v;
}

// Block-exclusive DS scan over one value per thread (PNT=1024 = 32 warps).
__device__ __forceinline__ DS block_excl(DS v, float2* swarp, int lane, int wid) {
    DS inc = warp_scan_incl(v, lane);
    if (lane == 31) swarp[wid] = ds_pack(inc);
    __syncthreads();
    if (wid == 0) {
        DS t = ds_of(swarp[lane]);
        t = warp_scan_incl(t, lane);
        swarp[lane] = ds_pack(t);
    }
    __syncthreads();
    DS warpOff = (wid > 0) ? ds_of(swarp[wid - 1]) : ds_make(0.f);
    float hh = __shfl_up_sync(0xFFFFFFFFu, inc.hi, 1);
    float ll = __shfl_up_sync(0xFFFFFFFFu, inc.lo, 1);
    DS exw;
    if (lane > 0) { exw.hi = hh; exw.lo = ll; } else exw = ds_make(0.f);
    DS r = ds_add2(warpOff, exw);
    __syncthreads();   // safe smem reuse by next call
    return r;
}

// ---------------- fused precompute (one block) --------------------------------
__global__ __launch_bounds__(PNT)
void precompute_kernel(const float* __restrict__ acts) {
    __shared__ float2 swarp[32];
    __shared__ int shMax;
    const int tid  = threadIdx.x;
    const int lane = tid & 31;
    const int wid  = tid >> 5;
    const int base = tid * PNP;

    #pragma unroll
    for (int k = 0; k < BATCH / PNT; k++) g_td[tid + k * PNT] = T_MAX;
    if (tid == 0) { shMax = -1; g_done = 0u; }

    // ---- load + per-element f,d ; thread-local DS sum of d ----
    float f[PNP], d[PNP];
    DS locD = ds_make(0.f);
    #pragma unroll
    for (int k = 0; k < PNP; k++) {
        int t = base + k;
        if (t < T_MAX) {
            f[k] = __expf(acts[t]);
            d[k] = LOG_GAMMA_F + log1pf(-f[k]);
            locD = ds_add(locD, d[k]);
        } else { f[k] = 0.f; d[k] = 0.f; }
    }
    __syncthreads();
    DS exD = block_excl(locD, swarp, lane, wid);

    // ---- serial pass: local sums of e and w ----
    DS run = ds_add2(ds_make(INIT_LOGW_F), exD);
    DS locE = ds_make(0.f), locW = ds_make(0.f);
    #pragma unroll
    for (int k = 0; k < PNP; k++) {
        int t = base + k;
        if (t < T_MAX) {
            float e = ALPHA_F * f[k] * __expf(run.hi);   // logw BEFORE update
            locE = ds_add(locE, e);
            run = ds_add(run, d[k]);
            float w = __expf(run.hi * 1.0e-3f);          // logw AFTER update
            locW = ds_add(locW, w);
        }
    }
    DS exE = block_excl(locE, swarp, lane, wid);
    DS exW = block_excl(locW, swarp, lane, wid);

    // ---- apply pass: m, c, prefW ----
    DS runP = ds_add2(ds_make(INIT_LOGP_F), exE);
    DS runW = exW;
    run = ds_add2(ds_make(INIT_LOGW_F), exD);
    int locMax = -1;
    #pragma unroll
    for (int k = 0; k < PNP; k++) {
        int t = base + k;
        if (t < T_MAX) {
            float p = __expf(runP.hi);
            float m = p / (1.0f - p) - EPS_F;
            g_m[t] = m;
            // conservative filter threshold with absolute slack (superset of triggers)
            g_c[t] = (m > 0.f) ? (__expf(-L1MIN_MAG * m) - 1.0e-6f) : 2.0f;
            if (m > 0.f) locMax = t;

            float e = ALPHA_F * f[k] * __expf(run.hi);
            run = ds_add(run, d[k]);
            float w = __expf(run.hi * 1.0e-3f);

            g_prefW[t] = runW.hi;
            runP = ds_add(runP, e);
            runW = ds_add(runW, w);
            if (t == T_MAX - 1) g_prefW[T_MAX] = runW.hi;
        }
    }
    atomicMax(&shMax, locMax);
    __syncthreads();
    if (tid == 0) g_TcutM1 = shMax;
}

// rare-path per-row handler (checks full trigger condition per element)
__device__ __forceinline__ void row_check(float4 v2, const float* p1row,
                                          float mi, float ci, int t,
                                          unsigned& done, int* ht) {
    float4 v1 = *(const float4*)p1row;
    if (!(done & 1u) && v2.x > ci &&
        __logf(v2.x + EPS_F) > mi * __logf(v1.x + EPS_F)) { done |= 1u; ht[0] = t; }
    if (!(done & 2u) && v2.y > ci &&
        __logf(v2.y + EPS_F) > mi * __logf(v1.y + EPS_F)) { done |= 2u; ht[1] = t; }
    if (!(done & 4u) && v2.z > ci &&
        __logf(v2.z + EPS_F) > mi * __logf(v1.z + EPS_F)) { done |= 4u; ht[2] = t; }
    if (!(done & 8u) && v2.w > ci &&
        __logf(v2.w + EPS_F) > mi * __logf(v1.w + EPS_F)) { done |= 8u; ht[3] = t; }
}

// ---------------- scan + fused finalize ---------------------------------------
__global__ __launch_bounds__(SNT)
void scan_kernel(const float* __restrict__ u1, const float* __restrict__ u2,
                 float* __restrict__ out) {
    __shared__ float sm[CHUNK];
    __shared__ float sc[CHUNK];
    __shared__ bool sLast;

    const int tid = threadIdx.x;
    const int t0  = blockIdx.y * CHUNK;
    const int Tc  = g_TcutM1 + 1;

    if (t0 >= Tc) return;   // dead block: no g_td writes possible, skip protocol

    if (tid < CHUNK) {
        int tt = t0 + tid;
        bool live = tt < Tc;                // Tc <= T_MAX so reads stay in-bounds
        sm[tid] = live ? g_m[tt] : 0.f;
        sc[tid] = live ? g_c[tt] : 2.0f;    // 2.0 => filter never passes
    }
    __syncthreads();

    const int b = (blockIdx.x * SNT + tid) * 4;   // 4 consecutive batch elems
    const float* p2 = u2 + (size_t)t0 * BATCH + b;
    const float* p1 = u1 + (size_t)t0 * BATCH + b;

    // batch ALL CHUNK loads up front (MLP = CHUNK per thread)
    float4 r[CHUNK];
    #pragma unroll
    for (int i = 0; i < CHUNK; i++)
        r[i] = *(const float4*)(p2 + (size_t)i * BATCH);

    unsigned done = 0;
    int ht[4] = {0, 0, 0, 0};
    bool any = false;
    bool a[CHUNK];
    #pragma unroll
    for (int i = 0; i < CHUNK; i++) {
        float x = fmaxf(fmaxf(r[i].x, r[i].y), fmaxf(r[i].z, r[i].w));
        a[i] = x > sc[i];
        any |= a[i];
    }
    if (any) {                              // rare path (~20% of threads)
        #pragma unroll
        for (int i = 0; i < CHUNK; i++) {
            if (a[i]) {
                row_check(r[i], p1 + (size_t)i * BATCH, sm[i], sc[i], t0 + i, done, ht);
                if (done == 0xFu) break;
            }
        }
        if (done & 1u) atomicMin(&g_td[b + 0], ht[0]);
        if (done & 2u) atomicMin(&g_td[b + 1], ht[1]);
        if (done & 4u) atomicMin(&g_td[b + 2], ht[2]);
        if (done & 8u) atomicMin(&g_td[b + 3], ht[3]);
    }

    // ---- completion protocol among LIVE blocks only ----
    const unsigned liveBlocks = (unsigned)SGX * (unsigned)((Tc + CHUNK - 1) / CHUNK);
    __syncthreads();
    if (tid == 0) {
        __threadfence();
        unsigned prev = atomicAdd(&g_done, 1u);
        sLast = (prev == liveBlocks - 1u);
    }
    __syncthreads();
    if (!sLast) return;
    __threadfence();

    __shared__ double sh[SNT];
    double s = 0.0;
    #pragma unroll
    for (int k = 0; k < BATCH / SNT; k++) {
        int bb = tid + k * SNT;
        s += (double)g_prefW[g_td[bb]];
    }
    sh[tid] = s;
    __syncthreads();
    #pragma unroll
    for (int ofs = SNT / 2; ofs > 0; ofs >>= 1) {
        if (tid < ofs) sh[tid] += sh[tid + ofs];
        __syncthreads();
    }
    if (tid == 0) out[0] = (float)(sh[0] * (1.0 / (double)BATCH));
}

// ---------------- launch -----------------------------------------------------
extern "C" void kernel_launch(void* const* d_in, const int* in_sizes, int n_in,
                              void* d_out, int out_size) {
    const float* acts = (const float*)d_in[0];
    const float* u1   = (const float*)d_in[1];
    const float* u2   = (const float*)d_in[2];
    float* out = (float*)d_out;

    precompute_kernel<<<1, PNT>>>(acts);
    dim3 grid(SGX, NCHUNKS);
    scan_kernel<<<grid, SNT>>>(u1, u2, out);
}